// round 5
// baseline (speedup 1.0000x reference)
#include <cuda_runtime.h>
#include <cuda_bf16.h>
#include <cstdint>

// Problem constants
#define Bb    32
#define Ll    4096
#define Cc    128
#define OUTD  257          // 1 delta + 128 probs + 128 amt
#define CL    256          // stored steps per block
#define HALO  192          // 0.9^192 ~ 1.6e-9 -> below fp32 noise
#define MAXN  (CL + HALO)  // 448
#define TT    16           // rows per staged tile
#define NTILE (CL / TT)    // 16

#define MOM   0.9f
#define OMM   0.1f
#define LOG2_MOM (-0.15200309344504995f)   // log2(0.9)

__device__ __forceinline__ uint32_t smem_u32(const void* p) {
    uint32_t a;
    asm("{ .reg .u64 t; cvta.to.shared.u64 t, %1; cvt.u32.u64 %0, t; }"
        : "=r"(a) : "l"(p));
    return a;
}

__global__ __launch_bounds__(160, 5)
void mpe_kernel(const float* __restrict__ ts,
                const int*   __restrict__ labels,
                const float* __restrict__ amounts,
                float*       __restrict__ out)
{
    __shared__ uint2 s_la[MAXN];                        // label bits, amount bits
    __shared__ float s_dl[MAXN];                        // clipped deltas
    __shared__ __align__(16) float s_out[2][TT * OUTD]; // staged output rows
    __shared__ float s_pacc[Cc];                        // warm-state accumulators
    __shared__ float s_aacc[Cc];
    __shared__ float s_dacc;

    const int chunk = blockIdx.x;
    const int b     = blockIdx.y;
    const int t0    = chunk * CL;
    const int s0    = (t0 - HALO) > 0 ? (t0 - HALO) : 0;
    const int N     = t0 + CL - s0;
    const int warm  = t0 - s0;
    const int tid   = threadIdx.x;

    const float* tsb = ts      + (size_t)b * Ll;
    const int*   lb  = labels  + (size_t)b * Ll;
    const float* ab  = amounts + (size_t)b * Ll;

    // ---- zero accumulators + cooperative preload ----
    if (tid < Cc)       { s_pacc[tid] = 0.0f; s_aacc[tid] = 0.0f; }
    else if (tid == Cc) { s_dacc = 0.0f; }

    for (int i = tid; i < N; i += blockDim.x) {
        const int g = s0 + i;
        s_la[i] = make_uint2((unsigned)lb[g], __float_as_uint(ab[g]));
        float d = 0.0f;
        if (g > 0) d = fminf(tsb[g] - tsb[g - 1], 100.0f);
        s_dl[i] = d;
    }
    __syncthreads();

    // ---- warm-up via weighted scatter (replaces the O(C*warm) scan) ----
    // state_after_warm = init*0.9^warm + sum_i 0.1*0.9^(warm-1-i)*x_i
    // x_i is one-hot in channel space -> 2 smem atomics per item.
    if (warm > 0) {
        float dsum = 0.0f;
        for (int i = tid; i < warm; i += blockDim.x) {
            const uint2 v = s_la[i];
            const float w = OMM * exp2f((float)(warm - 1 - i) * LOG2_MOM);
            atomicAdd(&s_pacc[v.x], w);
            atomicAdd(&s_aacc[v.x], w * __uint_as_float(v.y));
            dsum += w * s_dl[i];
        }
        atomicAdd(&s_dacc, dsum);
        if (s0 == 0 && tid == 0) {
            // exact-start init term: carry = x0 contributes 0.9^warm * x0
            const uint2 v0 = s_la[0];
            const float w0 = exp2f((float)warm * LOG2_MOM);
            atomicAdd(&s_pacc[v0.x], w0);
            atomicAdd(&s_aacc[v0.x], w0 * __uint_as_float(v0.y));
            // delta: dl[0] == 0 -> no init term
        }
        __syncthreads();
    }

    // ---- load per-thread scan state ----
    float p = 0.0f, a = 0.0f, dcar = 0.0f;
    const int c = tid;
    if (tid < Cc) {
        p = s_pacc[tid];
        a = s_aacc[tid];
        if (warm == 0) {            // chunk 0: exact carry-init (s0 == 0)
            const uint2 la0 = s_la[0];
            const bool eq0 = ((int)la0.x == c);
            p = eq0 ? 1.0f : 0.0f;
            a = eq0 ? __uint_as_float(la0.y) : 0.0f;
        }
    } else if (tid == Cc) {
        dcar = s_dacc;              // ==0 for chunk 0
    }

    // ---- stored steps: scan into smem tiles, drain via cp.async.bulk ----
    const char* gbase = (const char*)(out + (size_t)(b * Ll + t0) * OUTD);
    int pb = 0;
    for (int tile = 0; tile < NTILE; tile++) {
        float* ob = s_out[pb];
        const int base = warm + tile * TT;

        if (tid < Cc) {
            const uint2* la = s_la + base;
            #pragma unroll
            for (int j = 0; j < TT; j++) {
                const uint2 v = la[j];
                const bool eq = ((int)v.x == c);
                p = MOM * p + (eq ? OMM : 0.0f);
                a = MOM * a + (eq ? OMM * __uint_as_float(v.y) : 0.0f);
                ob[j * OUTD + 1 + c]      = p;                              // probs (sum==1)
                ob[j * OUTD + 1 + Cc + c] = __fdividef(a, fmaxf(p, 1e-6f)); // amt
            }
        } else if (tid == Cc) {
            const float* dl = s_dl + base;
            #pragma unroll
            for (int j = 0; j < TT; j++) {
                dcar = MOM * dcar + OMM * dl[j];
                ob[j * OUTD] = dcar;
            }
        }
        __syncthreads();   // tile fully written

        if (tid == Cc + 1) {
            asm volatile("fence.proxy.async.shared::cta;" ::: "memory");
            const uint64_t gdst = (uint64_t)(gbase + (size_t)tile * TT * OUTD * 4);
            const uint32_t ssrc = smem_u32(ob);
            asm volatile("cp.async.bulk.global.shared::cta.bulk_group [%0], [%1], %2;"
                         :: "l"(gdst), "r"(ssrc), "r"((uint32_t)(TT * OUTD * 4))
                         : "memory");
            asm volatile("cp.async.bulk.commit_group;" ::: "memory");
            asm volatile("cp.async.bulk.wait_group 1;" ::: "memory");
        }
        __syncthreads();   // other buffer drained -> reusable
        pb ^= 1;
    }

    if (tid == Cc + 1)
        asm volatile("cp.async.bulk.wait_group 0;" ::: "memory");
}

extern "C" void kernel_launch(void* const* d_in, const int* in_sizes, int n_in,
                              void* d_out, int out_size)
{
    const float* ts      = (const float*)d_in[0];
    const int*   labels  = (const int*)  d_in[1];
    const float* amounts = (const float*)d_in[2];
    float* out = (float*)d_out;

    dim3 grid(Ll / CL, Bb);   // (16, 32) = 512 blocks
    dim3 block(160);
    mpe_kernel<<<grid, block>>>(ts, labels, amounts, out);
}

// round 6
// speedup vs baseline: 1.0535x; 1.0535x over previous
#include <cuda_runtime.h>
#include <cuda_bf16.h>
#include <cstdint>

// Problem constants
#define Bb    32
#define Ll    4096
#define Cc    128
#define OUTD  257          // 1 delta + 128 probs + 128 amt
#define CL    256          // stored steps per block
#define HALO  192          // 0.9^192 ~ 1.6e-9 -> below fp32 noise
#define MAXN  (CL + HALO)  // 448
#define TT    16           // rows per staged tile (== unroll depth of q-space tile)
#define NTILE (CL / TT)    // 16

#define MOM   0.9f
#define OMM   0.1f
#define LOG2_MOM (-0.15200309344504995f)   // log2(0.9)

__device__ __forceinline__ uint32_t smem_u32(const void* p) {
    uint32_t a;
    asm("{ .reg .u64 t; cvta.to.shared.u64 t, %1; cvt.u32.u64 %0, t; }"
        : "=r"(a) : "l"(p));
    return a;
}

__global__ __launch_bounds__(160, 5)
void mpe_kernel(const float* __restrict__ ts,
                const int*   __restrict__ labels,
                const float* __restrict__ amounts,
                float*       __restrict__ out)
{
    __shared__ int   s_lab[MAXN];                       // labels
    __shared__ float s_amt[MAXN];                       // amounts
    __shared__ float s_dl[MAXN];                        // clipped deltas
    __shared__ __align__(16) float s_out[2][TT * OUTD]; // staged output rows
    __shared__ float s_pacc[Cc];                        // warm-state accumulators
    __shared__ float s_aacc[Cc];
    __shared__ float s_dacc;

    // 0.9^(j+1) and 0.1*0.9^-(j+1): compile-time immediates in the unrolled tile
    constexpr float SC[16] = {
        0.9f, 0.81f, 0.729f, 0.6561f, 0.59049f, 0.531441f, 0.4782969f,
        0.43046721f, 0.387420489f, 0.3486784401f, 0.31381059609f,
        0.282429536481f, 0.2541865828329f, 0.22876792454961f,
        0.205891132094649f, 0.1853020188851841f };
    constexpr float WC[16] = {
        0.111111111111111f, 0.123456790123457f, 0.137174211248285f,
        0.152415790275873f, 0.169350878084303f, 0.188167642315892f,
        0.209075158128769f, 0.232305731254188f, 0.258117479171320f,
        0.286797199079244f, 0.318663554532493f, 0.354070616147215f,
        0.393411795719128f, 0.437124217465697f, 0.485693574961886f,
        0.539659527735429f };

    const int chunk = blockIdx.x;
    const int b     = blockIdx.y;
    const int t0    = chunk * CL;
    const int s0    = (t0 - HALO) > 0 ? (t0 - HALO) : 0;
    const int N     = t0 + CL - s0;
    const int warm  = t0 - s0;
    const int tid   = threadIdx.x;

    const float* tsb = ts      + (size_t)b * Ll;
    const int*   lb  = labels  + (size_t)b * Ll;
    const float* ab  = amounts + (size_t)b * Ll;

    // ---- zero accumulators + cooperative preload ----
    if (tid < Cc)       { s_pacc[tid] = 0.0f; s_aacc[tid] = 0.0f; }
    else if (tid == Cc) { s_dacc = 0.0f; }

    for (int i = tid; i < N; i += blockDim.x) {
        const int g = s0 + i;
        s_lab[i] = lb[g];
        s_amt[i] = ab[g];
        float d = 0.0f;
        if (g > 0) d = fminf(tsb[g] - tsb[g - 1], 100.0f);
        s_dl[i] = d;
    }
    __syncthreads();

    // ---- warm-up via weighted scatter: state = sum_i 0.1*0.9^(warm-1-i)*x_i ----
    if (warm > 0) {
        float dsum = 0.0f;
        for (int i = tid; i < warm; i += blockDim.x) {
            const float w = OMM * exp2f((float)(warm - 1 - i) * LOG2_MOM);
            atomicAdd(&s_pacc[s_lab[i]], w);
            atomicAdd(&s_aacc[s_lab[i]], w * s_amt[i]);
            dsum += w * s_dl[i];
        }
        atomicAdd(&s_dacc, dsum);
        if (s0 == 0 && tid == 0) {
            // exact-start init: carry = x0 contributes 0.9^warm * x0
            const float w0 = exp2f((float)warm * LOG2_MOM);
            atomicAdd(&s_pacc[s_lab[0]], w0);
            atomicAdd(&s_aacc[s_lab[0]], w0 * s_amt[0]);
        }
        __syncthreads();
    }

    // ---- load per-thread scan state (q-space) ----
    float q = 0.0f, qa = 0.0f, r = 0.0f, dcar = 0.0f;
    const int c = tid;
    if (tid < Cc) {
        float p0, a0;
        if (warm == 0) {            // chunk 0: exact carry-init (y[0] = x[0])
            const bool eq0 = (s_lab[0] == c);
            p0 = eq0 ? 1.0f : 0.0f;
            a0 = eq0 ? s_amt[0] : 0.0f;
        } else {
            p0 = s_pacc[tid];
            a0 = s_aacc[tid];
        }
        q  = p0;
        qa = a0;
        r  = __fdividef(a0, fmaxf(p0, 1e-30f));  // a0==0 when p0==0 -> r=0
    } else if (tid == Cc) {
        dcar = s_dacc;              // ==0 for chunk 0
    }

    // ---- stored steps: sparse-hit scan into smem tiles, bulk-copy drain ----
    const char* gbase = (const char*)(out + (size_t)(b * Ll + t0) * OUTD);
    int pb = 0;
    for (int tile = 0; tile < NTILE; tile++) {
        float* ob = s_out[pb];
        const int base = warm + tile * TT;

        if (tid < Cc) {
            #pragma unroll
            for (int j = 0; j < TT; j++) {
                const bool eq = (s_lab[base + j] == c);
                // uniform skip: 78% of steps no lane in this warp hits
                if (__ballot_sync(0xffffffffu, eq)) {
                    if (eq) {
                        q  += WC[j];                          // 0.1*0.9^-(j+1)
                        qa  = fmaf(s_amt[base + j], WC[j], qa);
                        const float ph = SC[j] * q;           // p at hit (>= 0.1)
                        const float ah = SC[j] * qa;
                        r = __fdividef(ah, ph);
                    }
                }
                const float pj = SC[j] * q;                   // probs (sum==1)
                const float a6 = (SC[j] * 1e6f) * qa;         // a / 1e-6
                const float amt = fminf(r, a6);               // == a/max(p,1e-6)
                ob[j * OUTD + 1 + c]      = pj;
                ob[j * OUTD + 1 + Cc + c] = amt;
            }
            // tile-boundary rescale back to true state space
            q  *= SC[TT - 1];
            qa *= SC[TT - 1];
        } else if (tid == Cc) {
            const float* dl = s_dl + base;
            #pragma unroll
            for (int j = 0; j < TT; j++) {
                dcar = MOM * dcar + OMM * dl[j];
                ob[j * OUTD] = dcar;
            }
        }
        __syncthreads();   // tile fully written

        if (tid == Cc + 1) {
            asm volatile("fence.proxy.async.shared::cta;" ::: "memory");
            const uint64_t gdst = (uint64_t)(gbase + (size_t)tile * TT * OUTD * 4);
            const uint32_t ssrc = smem_u32(ob);
            asm volatile("cp.async.bulk.global.shared::cta.bulk_group [%0], [%1], %2;"
                         :: "l"(gdst), "r"(ssrc), "r"((uint32_t)(TT * OUTD * 4))
                         : "memory");
            asm volatile("cp.async.bulk.commit_group;" ::: "memory");
            asm volatile("cp.async.bulk.wait_group 1;" ::: "memory");
        }
        __syncthreads();   // other buffer drained -> reusable
        pb ^= 1;
    }

    if (tid == Cc + 1)
        asm volatile("cp.async.bulk.wait_group 0;" ::: "memory");
}

extern "C" void kernel_launch(void* const* d_in, const int* in_sizes, int n_in,
                              void* d_out, int out_size)
{
    const float* ts      = (const float*)d_in[0];
    const int*   labels  = (const int*)  d_in[1];
    const float* amounts = (const float*)d_in[2];
    float* out = (float*)d_out;

    dim3 grid(Ll / CL, Bb);   // (16, 32) = 512 blocks
    dim3 block(160);
    mpe_kernel<<<grid, block>>>(ts, labels, amounts, out);
}